// round 12
// baseline (speedup 1.0000x reference)
#include <cuda_runtime.h>
#include <cuda_bf16.h>
#include <math.h>

#define NBINS 32
#define TILE  256          // elements per block-iteration (halves barrier rate)
#define NT    256
#define GBLK  444          // 148 SMs * 3 resident blocks
#define RQ    9            // smem row stride in float4 (8 data quads + 1 pad)
#define NCELL (NBINS * NBINS)
#define BUFQ  (2 * TILE * RQ)                       // float4s: WA + WB
#define SMEM_BYTES (BUFQ * (int)sizeof(float4))     // 73,728 B dynamic

typedef unsigned long long ull;

// ---------------- scratch (no allocations allowed) ----------------
__device__ unsigned g_minbits;
__device__ unsigned g_maxbits;
__device__ int      g_arrived;              // reduce->final handoff counter
__device__ float    g_part[NCELL * GBLK];   // [cell][block] fp32 partials (~1.8 MB)
__device__ double   g_pab[NCELL];           // fp64 joint histogram sums

// order-preserving encoding so uint atomicMin/Max give exact float min/max
__device__ __forceinline__ unsigned enc_f(float v) {
    unsigned u = __float_as_uint(v);
    return (u & 0x80000000u) ? ~u : (u | 0x80000000u);
}
__device__ __forceinline__ float dec_f(unsigned u) {
    return (u & 0x80000000u) ? __uint_as_float(u & 0x7FFFFFFFu)
                             : __uint_as_float(~u);
}

// ---- packed fp32x2 ops: each half is an exact IEEE fp32 op (asm -> ptxas
// cannot reassociate the weight chain) ----
__device__ __forceinline__ ull add2(ull a, ull b) {
    ull r; asm("add.rn.f32x2 %0, %1, %2;" : "=l"(r) : "l"(a), "l"(b)); return r;
}
__device__ __forceinline__ ull mul2(ull a, ull b) {
    ull r; asm("mul.rn.f32x2 %0, %1, %2;" : "=l"(r) : "l"(a), "l"(b)); return r;
}
__device__ __forceinline__ void ffma2(ull& d, ull a, ull b) {
    asm("fma.rn.f32x2 %0, %1, %2, %0;" : "+l"(d) : "l"(a), "l"(b));
}
__device__ __forceinline__ ull dup_f32(float v) {
    ull r; asm("mov.b64 %0, {%1, %1};" : "=l"(r) : "r"(__float_as_uint(v))); return r;
}
__device__ __forceinline__ void unpk(float& lo, float& hi, ull v) {
    asm("mov.b64 {%0, %1}, %2;" : "=f"(lo), "=f"(hi) : "l"(v));
}
// exact __expf lowering: __expf(x) == ex2.approx(x * 0x3FB8AA3B)
__device__ __forceinline__ float ex2f(float x) {
    float r; asm("ex2.approx.f32 %0, %1;" : "=f"(r) : "f"(x)); return r;
}

__global__ void mi_init() {
    g_minbits = 0xFFFFFFFFu;
    g_maxbits = 0u;
    g_arrived = 0;
}

// no-op probe: keeps mi_main at global launch index 5 for ncu (-s 5 -c 1)
__global__ void mi_probe() {}

__global__ void mi_minmax(const float* __restrict__ p,
                          const float* __restrict__ t, int N) {
    unsigned lmin = 0xFFFFFFFFu, lmax = 0u;
    int stride = gridDim.x * blockDim.x;
    int gtid = blockIdx.x * blockDim.x + threadIdx.x;
    int n4 = N >> 2;
    const float4* p4 = (const float4*)p;
    const float4* t4 = (const float4*)t;
    for (int i = gtid; i < n4; i += stride) {
        float4 a = __ldg(p4 + i);
        float4 b = __ldg(t4 + i);
        unsigned u;
        u = enc_f(a.x); lmin = min(lmin, u); lmax = max(lmax, u);
        u = enc_f(a.y); lmin = min(lmin, u); lmax = max(lmax, u);
        u = enc_f(a.z); lmin = min(lmin, u); lmax = max(lmax, u);
        u = enc_f(a.w); lmin = min(lmin, u); lmax = max(lmax, u);
        u = enc_f(b.x); lmin = min(lmin, u); lmax = max(lmax, u);
        u = enc_f(b.y); lmin = min(lmin, u); lmax = max(lmax, u);
        u = enc_f(b.z); lmin = min(lmin, u); lmax = max(lmax, u);
        u = enc_f(b.w); lmin = min(lmin, u); lmax = max(lmax, u);
    }
    for (int i = (n4 << 2) + gtid; i < N; i += stride) {   // tail
        unsigned u = enc_f(__ldg(p + i));
        lmin = min(lmin, u); lmax = max(lmax, u);
        u = enc_f(__ldg(t + i));
        lmin = min(lmin, u); lmax = max(lmax, u);
    }
#pragma unroll
    for (int o = 16; o > 0; o >>= 1) {
        lmin = min(lmin, __shfl_xor_sync(0xFFFFFFFFu, lmin, o));
        lmax = max(lmax, __shfl_xor_sync(0xFFFFFFFFu, lmax, o));
    }
    __shared__ unsigned smin[8], smax[8];
    int wid = threadIdx.x >> 5;
    if ((threadIdx.x & 31) == 0) { smin[wid] = lmin; smax[wid] = lmax; }
    __syncthreads();
    if (threadIdx.x == 0) {
        unsigned m = smin[0], M = smax[0];
        int nw = blockDim.x >> 5;
        for (int w = 1; w < nw; w++) { m = min(m, smin[w]); M = max(M, smax[w]); }
        atomicMin(&g_minbits, m);   // exact, order-independent -> deterministic
        atomicMax(&g_maxbits, M);
    }
}

// Main kernel. Per-element weight values are BIT-IDENTICAL to the validated
// R9 arithmetic: d = x + (-c) (negation exact), npre*d, *d, *log2e each an
// exact fp32 op (packed f32x2 asm), ex2.approx == __expf lowering, S summed
// in the same k-ascending scalar order, same 1/S, same scale multiply.
// Changes: 256-element iterations (each thread does its pred AND tgt row;
// half the barriers) and asm-locked packed weight math (fewer fma-pipe ops,
// immune to ptxas reassociation).
__global__ __launch_bounds__(NT, 3)
void mi_main(const float* __restrict__ pred, const float* __restrict__ tgt,
             int N, int numTiles) {
    extern __shared__ float4 SH[];         // WA[256*RQ] then WB[256*RQ]
    __shared__ float4 CBn[8];              // NEGATED bin centers
    float4* WA = SH;
    float4* WB = SH + TILE * RQ;
    const ull* CBu = (const ull*)CBn;

    float minv = dec_f(g_minbits);
    float maxv = dec_f(g_maxbits);
    if (maxv <= 1.0f && minv >= 0.0f) { minv = 0.0f; maxv = 1.0f; }
    float range  = maxv - minv;
    const float inv31 = 1.0f / 31.0f;
    float sigma  = range / 31.0f;                 // /(NUM_BINS-1) * SIGMA_RATIO(=1)
    float preterm = 1.0f / ((2.0f * sigma) * sigma);
    float npre   = 0.0f - preterm;

    int t = threadIdx.x;
    if (t < 8) {   // same center expression as validated, then exact negation
        float4 cq;
        cq.x = -(minv + range * ((float)(4 * t + 0) * inv31));
        cq.y = -(minv + range * ((float)(4 * t + 1) * inv31));
        cq.z = -(minv + range * ((float)(4 * t + 2) * inv31));
        cq.w = -(minv + range * ((float)(4 * t + 3) * inv31));
        CBn[t] = cq;
    }

    ull NP2 = dup_f32(npre);
    ull L2E = dup_f32(__uint_as_float(0x3FB8AA3Bu));  // log2(e), __expf constant

    // FMA-phase roles
    int warp = t >> 5;            // elements [warp*32, warp*32+32)
    int lane = t & 31;
    int kp   = lane >> 3;         // k-block: rows kp*8 .. kp*8+7
    int lp   = lane & 7;          // l-block: cols lp*4 .. lp*4+3
    const float4* Arow0 = WA + (warp * 32) * RQ + 2 * kp;
    const float4* Brow0 = WB + (warp * 32) * RQ + lp;

    ull acc2[4][4];
#pragma unroll
    for (int rp = 0; rp < 4; rp++)
#pragma unroll
        for (int c = 0; c < 4; c++) acc2[rp][c] = 0ull;

    for (int tile = blockIdx.x; tile < numTiles; tile += gridDim.x) {
        __syncthreads();                  // prev FMA reads done; CBn visible (1st)
        int idx = tile * TILE + t;
        bool valid = (idx < N);

        // weight phase: this thread's pred row, then its tgt row
#pragma unroll
        for (int sel = 0; sel < 2; sel++) {
            const float* src = sel ? tgt : pred;
            float4* Wrow = (sel ? WB : WA) + t * RQ;
            unsigned waddr = (unsigned)__cvta_generic_to_shared(Wrow);
            float x = valid ? __ldg(src + idx) : 0.0f;
            ull X2 = dup_f32(x);
            float S = 0.0f;
#pragma unroll
            for (int q = 0; q < 8; q++) {
                ull c01 = CBu[2 * q], c23 = CBu[2 * q + 1];
                ull d01 = add2(X2, c01), d23 = add2(X2, c23);
                ull t01 = mul2(NP2, d01), t23 = mul2(NP2, d23);
                ull a01 = mul2(t01, d01), a23 = mul2(t23, d23);
                ull e01 = mul2(a01, L2E), e23 = mul2(a23, L2E);
                float y0, y1, y2, y3;
                unpk(y0, y1, e01); unpk(y2, y3, e23);
                float4 v;
                v.x = ex2f(y0); v.y = ex2f(y1); v.z = ex2f(y2); v.w = ex2f(y3);
                S += v.x; S += v.y; S += v.z; S += v.w;   // same order as R9
                Wrow[q] = v;
            }
            float rsc = valid ? (1.0f / S) : 0.0f;
            ull R2 = dup_f32(rsc);
#pragma unroll
            for (int q = 0; q < 8; q++) {   // in-place scale, packed, no unpack
                ull lo, hi;
                asm("ld.shared.v2.b64 {%0, %1}, [%2];"
                    : "=l"(lo), "=l"(hi) : "r"(waddr + q * 16));
                lo = mul2(lo, R2); hi = mul2(hi, R2);
                asm("st.shared.v2.b64 [%0], {%1, %2};"
                    :: "r"(waddr + q * 16), "l"(lo), "l"(hi) : "memory");
            }
        }
        __syncthreads();

        // FMA phase: 32 elements, 8x4 outer product each, packed f32x2
#pragma unroll 4
        for (int e = 0; e < 32; e++) {
            float4 a0 = Arow0[e * RQ];
            float4 a1 = Arow0[e * RQ + 1];
            float4 b  = Brow0[e * RQ];
            ull ap[4];
            ap[0] = *(const ull*)&a0.x;   // {k0,k1}
            ap[1] = *(const ull*)&a0.z;   // {k2,k3}
            ap[2] = *(const ull*)&a1.x;   // {k4,k5}
            ap[3] = *(const ull*)&a1.z;   // {k6,k7}
            ull bb[4];
            bb[0] = dup_f32(b.x);
            bb[1] = dup_f32(b.y);
            bb[2] = dup_f32(b.z);
            bb[3] = dup_f32(b.w);
#pragma unroll
            for (int rp = 0; rp < 4; rp++)
#pragma unroll
                for (int c = 0; c < 4; c++)
                    ffma2(acc2[rp][c], ap[rp], bb[c]);
        }
    }

    // combine the 8 warps' accumulators (reuse SH as float[8][1024])
    __syncthreads();
    float* sred = (float*)SH;
#pragma unroll
    for (int rp = 0; rp < 4; rp++)
#pragma unroll
        for (int c = 0; c < 4; c++) {
            float lo, hi;
            unpk(lo, hi, acc2[rp][c]);
            int k0 = kp * 8 + 2 * rp;
            int l  = lp * 4 + c;
            sred[warp * 1024 + (k0    ) * NBINS + l] = lo;
            sred[warp * 1024 + (k0 + 1) * NBINS + l] = hi;
        }
    __syncthreads();
    // [cell][block] layout: contiguous per-cell rows for the reduce kernel
    for (int cell = t; cell < NCELL; cell += NT) {
        float s = 0.0f;
#pragma unroll
        for (int w = 0; w < 8; w++) s += sred[w * 1024 + cell];
        g_part[cell * GBLK + blockIdx.x] = s;
    }
}

// Fused second-stage reduction + MI epilogue (validated in R11).
__global__ void mi_reduce_final(float* __restrict__ out, int N) {
    __shared__ double sd[128];
    __shared__ double pa[NBINS], pb[NBINS];
    __shared__ int lastFlag;
    int cell = blockIdx.x;
    int t = threadIdx.x;
    const float* p = g_part + cell * GBLK;
    double s = 0.0;
    s += (double)p[t];                          // GBLK=444 > 128: t always valid
    s += (double)p[t + 128];
    s += (double)p[t + 256];
    if (t + 384 < GBLK) s += (double)p[t + 384];
    sd[t] = s;
    __syncthreads();
#pragma unroll
    for (int o = 64; o > 0; o >>= 1) {
        if (t < o) sd[t] = sd[t] + sd[t + o];   // fixed tree order -> deterministic
        __syncthreads();
    }
    if (t == 0) {
        g_pab[cell] = sd[0];
        __threadfence();
        int n = atomicAdd(&g_arrived, 1);
        lastFlag = (n == NCELL - 1) ? 1 : 0;
        if (lastFlag) g_arrived = 0;            // re-arm for next graph replay
    }
    __syncthreads();
    if (!lastFlag) return;
    __threadfence();                            // all g_pab writes visible

    double invN = 1.0 / (double)N;
    if (t < 32) {
        double sr = 0.0;
        for (int l = 0; l < NBINS; l++) sr += g_pab[t * NBINS + l];
        pa[t] = sr * invN;
    } else if (t < 64) {
        int l = t - 32;
        double sc = 0.0;
        for (int k = 0; k < NBINS; k++) sc += g_pab[k * NBINS + l];
        pb[l] = sc * invN;
    }
    __syncthreads();

    double acc = 0.0;
#pragma unroll
    for (int i = 0; i < 8; i++) {               // cells t, t+128, ... (fixed order)
        int c2 = t + i * 128;
        int k = c2 >> 5, l = c2 & 31;
        double pab  = g_pab[c2] * invN;
        double papb = pa[k] * pb[l];
        acc += pab * log((pab + 1e-7) / (papb + 1e-7) + 1e-7);
    }
    sd[t] = acc;
    __syncthreads();
#pragma unroll
    for (int o = 64; o > 0; o >>= 1) {
        if (t < o) sd[t] = sd[t] + sd[t + o];   // fixed tree -> deterministic
        __syncthreads();
    }
    if (t == 0) *out = (float)(-sd[0]);
}

extern "C" void kernel_launch(void* const* d_in, const int* in_sizes, int n_in,
                              void* d_out, int out_size) {
    const float* pred = (const float*)d_in[0];
    const float* tgt  = (const float*)d_in[1];
    int N = in_sizes[0];
    int numTiles = (N + TILE - 1) / TILE;

    // allow >48KB dynamic smem (host-side attribute; not a graph node)
    cudaFuncSetAttribute(mi_main, cudaFuncAttributeMaxDynamicSharedMemorySize,
                         SMEM_BYTES);

    mi_init<<<1, 1>>>();
    mi_minmax<<<1184, 256>>>(pred, tgt, N);
    mi_probe<<<1, 1>>>();   // keeps mi_main at ncu capture slot (launch idx 5)
    mi_main<<<GBLK, NT, SMEM_BYTES>>>(pred, tgt, N, numTiles);
    mi_reduce_final<<<NCELL, 128>>>((float*)d_out, N);
}